// round 17
// baseline (speedup 1.0000x reference)
#include <cuda_runtime.h>
#include <math.h>
#include <stdint.h>

// ---------------------------------------------------------------------------
// PPO fused loss on GB300 — warp-specialized, ring-3 (R16 + column-coverage
// fix in the producer GEMV):
//  consumers (warps 0..7): mma.sync tf32 actor logits + values (9 mma/kstep)
//  producers (warps 8..9): all cp.async (states + B window) AND the fp32
//    next_values GEMV (now BOTH float4 halves of each 32-col window).
// ---------------------------------------------------------------------------

#define T_MAX   262144
#define S_DIM   512
#define A_DIM   64
#define BM      128
#define GAMMA_F 0.99f
#define GL_F    (0.99f * 0.98f)
#define CLIP_LO 0.8f
#define CLIP_HI 1.2f
#define ENT_C   0.01f
#define CHUNK   2048
#define NB_MAX  (T_MAX / CHUNK)
#define NGRP    9
#define GRID1   304
#define NTHR    320
#define NCONS   256

// named barrier ids
#define BFULL0  1      // 1,2,3
#define BFREE0  4      // 4,5,6
#define BHDR    7
#define BEPI    8
#define BPROD   9

// scratch
__device__ float g_v[T_MAX];
__device__ float g_nv[T_MAX];
__device__ float g_ratio[T_MAX];
__device__ float g_ent[T_MAX / BM];
__device__ float g_cA[NB_MAX];
__device__ float g_cB[NB_MAX];
__device__ float g_surr[NB_MAX];
__device__ float g_adv2[NB_MAX];
__device__ int   g_tile;
__device__ int   g_flag;
__device__ int   g_flag2;
__device__ __align__(16) float2 g_wfrag[64 * NGRP * 32];

// ---------------- smem layout ----------------
#define SLABS        16
#define RING         3
#define A_ROW_F      36
#define SLAB_BYTES   (128 * 144)           // 18432
#define BW_BYTES     (4 * NGRP * 32 * 8)   // 9216
#define STAGE_BYTES  (SLAB_BYTES + BW_BYTES)     // 27648
#define OFF_SCW   (RING * STAGE_BYTES)     // 82944
#define OFF_ENT   (OFF_SCW + 2048)         // 84992
#define OFF_Q     (OFF_ENT + 64)           // 85056
#define SMEM_TOTAL (OFF_Q + 64)            // 85120 (x2 = 170240 <= 227KB)

// ---------------- PTX helpers ----------------
__device__ __forceinline__ uint32_t smem_to_u32(const void* p) {
    uint32_t a;
    asm("{ .reg .u64 t; cvta.to.shared.u64 t, %1; cvt.u32.u64 %0, t; }" : "=r"(a) : "l"(p));
    return a;
}
__device__ __forceinline__ void cpa16(uint32_t dst, const void* src) {
    asm volatile("cp.async.cg.shared.global [%0], [%1], 16;" :: "r"(dst), "l"(src) : "memory");
}
#define CP_COMMIT() asm volatile("cp.async.commit_group;" ::: "memory")
#define CP_WAIT2()  asm volatile("cp.async.wait_group 2;" ::: "memory")
#define CP_WAIT1()  asm volatile("cp.async.wait_group 1;" ::: "memory")
#define CP_WAIT0()  asm volatile("cp.async.wait_group 0;" ::: "memory")
#define BAR_SYNC(id, cnt)   asm volatile("bar.sync %0, %1;"   :: "r"(id), "r"(cnt) : "memory")
#define BAR_ARRIVE(id, cnt) asm volatile("bar.arrive %0, %1;" :: "r"(id), "r"(cnt) : "memory")

__device__ __forceinline__ void mma_tf32(float (&d)[4], const uint32_t (&a)[4],
                                         const uint32_t (&b)[2]) {
    asm volatile(
        "mma.sync.aligned.m16n8k8.row.col.f32.tf32.tf32.f32 "
        "{%0,%1,%2,%3}, {%4,%5,%6,%7}, {%8,%9}, {%0,%1,%2,%3};"
        : "+f"(d[0]), "+f"(d[1]), "+f"(d[2]), "+f"(d[3])
        : "r"(a[0]), "r"(a[1]), "r"(a[2]), "r"(a[3]), "r"(b[0]), "r"(b[1]));
}
__device__ __forceinline__ uint32_t to_tf32(float x) {
    uint32_t r;
    asm("cvt.rna.tf32.f32 %0, %1;" : "=r"(r) : "f"(x));
    return r;
}

// ---------------------------------------------------------------------------
// prep: pack [actor_w | critic_w] into mma B-fragment order + reset counters.
// ---------------------------------------------------------------------------
__global__ void kprep(const float* __restrict__ aw, const float* __restrict__ cw) {
    if (blockIdx.x == 0 && threadIdx.x == 0) { g_tile = 0; g_flag = 0; g_flag2 = 0; }
    int e = blockIdx.x * 256 + threadIdx.x;
    int lane = e & 31, gk = e >> 5;
    int G = gk % NGRP, ks = gk / NGRP;
    int nloc = lane >> 2;
    int k = ks * 8 + (lane & 3);
    float w0, w1;
    if (G < 8) {
        int n = G * 8 + nloc;
        w0 = aw[k * A_DIM + n];
        w1 = aw[(k + 4) * A_DIM + n];
    } else {
        w0 = (nloc == 0) ? cw[k] : 0.f;
        w1 = (nloc == 0) ? cw[k + 4] : 0.f;
    }
    float2 v;
    v.x = __uint_as_float(to_tf32(w0));
    v.y = __uint_as_float(to_tf32(w1));
    g_wfrag[e] = v;
}

// ---------------------------------------------------------------------------
// producer slab loader (64 threads): states slab + B window only.
// ---------------------------------------------------------------------------
__device__ __forceinline__ void issue_slab64(uint32_t su, int buf, int tile, int s,
                                             const float* __restrict__ states,
                                             int ptid) {
    const uint32_t sbase = su + buf * STAGE_BYTES;
    const size_t goff = (size_t)tile * BM * S_DIM + s * 32;
#pragma unroll
    for (int i = 0; i < 16; ++i) {
        int g = ptid + i * 64;                 // 0..1023
        int r = g >> 3, u = g & 7;
        cpa16(sbase + r * 144 + u * 16, states + goff + (size_t)r * S_DIM + u * 4);
    }
    const char* bsrc = (const char*)(g_wfrag + (size_t)s * 4 * NGRP * 32);
#pragma unroll
    for (int i = 0; i < 9; ++i) {
        int g = ptid + i * 64;                 // 0..575
        cpa16(sbase + SLAB_BYTES + g * 16, bsrc + (size_t)g * 16);
    }
}

// ---------------------------------------------------------------------------
// Main kernel
// ---------------------------------------------------------------------------
__global__ void __launch_bounds__(NTHR, 2)
k1_mma(const float* __restrict__ states,
       const float* __restrict__ next_states,
       const int*   __restrict__ actions,
       const float* __restrict__ log_probs,
       const float* __restrict__ actor_b,
       const float* __restrict__ critic_w,
       const float* __restrict__ critic_b,
       int nb1) {
    extern __shared__ __align__(16) char smem[];
    const uint32_t su = smem_to_u32(smem);
    const int tid  = threadIdx.x;
    const int w    = tid >> 5;
    const int lane = tid & 31;
    const float cb = critic_b[0];

    float* scw  = (float*)(smem + OFF_SCW);
    float* sEnt = (float*)(smem + OFF_ENT);
    int*   sQ   = (int*)(smem + OFF_Q);

    if (w >= 8) {
        // ===================== PRODUCERS (warps 8,9) =====================
        const int ptid = tid - NCONS;          // 0..63
        const int u  = ptid & 3;               // float4 pair selector
        const int rr = ptid >> 2;              // 0..15 (row within pass)
        ((float4*)scw)[ptid]      = __ldg(((const float4*)critic_w) + ptid);
        ((float4*)scw)[ptid + 64] = __ldg(((const float4*)critic_w) + ptid + 64);
        BAR_SYNC(BPROD, 64);

        int Lc = 0;                            // slabs issued so far
        for (int i = 0;; ++i) {
            if (ptid == 0) sQ[i & 7] = atomicAdd(&g_tile, 1);
            BAR_SYNC(BPROD, 64);
            const int t = sQ[i & 7];
            BAR_ARRIVE(BHDR, NTHR);
            if (t >= nb1) break;

            float nvacc[8];
#pragma unroll
            for (int p = 0; p < 8; ++p) nvacc[p] = 0.f;

#pragma unroll 1
            for (int s = 0; s < SLABS; ++s) {
                const int L = Lc;
                const int buf = L % RING;
                if (L >= RING) BAR_SYNC(BFREE0 + buf, NTHR);
                issue_slab64(su, buf, t, s, states, ptid);
                CP_COMMIT();
                if (L >= 2) {
                    CP_WAIT2();                       // group L-2 complete
                    BAR_ARRIVE(BFULL0 + ((L - 2) % RING), NTHR);
                }
                ++Lc;

                // fp32 next_values GEMV: BOTH float4 halves of the 32-col window
                const float4 wv0 = *(const float4*)&scw[s * 32 + u * 4];
                const float4 wv1 = *(const float4*)&scw[s * 32 + 16 + u * 4];
#pragma unroll
                for (int p = 0; p < 8; ++p) {
                    const int row = p * 16 + rr;
                    const float4* xs = (const float4*)(next_states
                                 + (size_t)(t * BM + row) * S_DIM + s * 32);
                    float4 x0 = __ldg(xs + u);
                    float4 x1 = __ldg(xs + 4 + u);
                    float a0 = fmaf(x0.x, wv0.x, fmaf(x0.y, wv0.y,
                               fmaf(x0.z, wv0.z, x0.w * wv0.w)));
                    nvacc[p] = fmaf(x1.x, wv1.x, fmaf(x1.y, wv1.y,
                               fmaf(x1.z, wv1.z, fmaf(x1.w, wv1.w,
                               nvacc[p] + a0))));
                }
            }
            // tile end: reduce over the 4 u-lanes of each row group, write g_nv
#pragma unroll
            for (int p = 0; p < 8; ++p) {
                float v = nvacc[p];
                v += __shfl_xor_sync(0xffffffffu, v, 1);
                v += __shfl_xor_sync(0xffffffffu, v, 2);
                if (u == 0) g_nv[t * BM + p * 16 + rr] = v + cb;
            }
        }
        // flush the last two FULL signals
        if (Lc >= 2) { CP_WAIT1(); BAR_ARRIVE(BFULL0 + ((Lc - 2) % RING), NTHR); }
        if (Lc >= 1) { CP_WAIT0(); BAR_ARRIVE(BFULL0 + ((Lc - 1) % RING), NTHR); }
        return;
    }

    // ===================== CONSUMERS (warps 0..7) =====================
    const int q = lane >> 2, j = lane & 3;

    float2 bias[8];
#pragma unroll
    for (int g = 0; g < 8; ++g)
        bias[g] = __ldg((const float2*)(actor_b + g * 8 + j * 2));

    int L = 0;
    for (int i = 0;; ++i) {
        BAR_SYNC(BHDR, NTHR);
        const int cur = sQ[i & 7];
        if (cur >= nb1) break;
        const int row0 = cur * BM;

        float acc[8][4];
        float accV[4];
#pragma unroll
        for (int g = 0; g < 8; ++g)
#pragma unroll
            for (int p = 0; p < 4; ++p) acc[g][p] = 0.f;
#pragma unroll
        for (int p = 0; p < 4; ++p) accV[p] = 0.f;

        for (int s = 0; s < SLABS; ++s, ++L) {
            const int buf = L % RING;
            BAR_SYNC(BFULL0 + buf, NTHR);       // slab resident

            const char* stage = smem + (size_t)buf * STAGE_BYTES;
            const float* Ar = (const float*)stage + (16 * w + q) * A_ROW_F + j;
            const float2* Bw = (const float2*)(stage + SLAB_BYTES);

#pragma unroll
            for (int ks = 0; ks < 4; ++ks) {
                uint32_t af[4];
                const float* Am = Ar + ks * 8;
                af[0] = __float_as_uint(Am[0]);
                af[1] = __float_as_uint(Am[8 * A_ROW_F]);
                af[2] = __float_as_uint(Am[4]);
                af[3] = __float_as_uint(Am[8 * A_ROW_F + 4]);

                const float2* Bk = Bw + (size_t)ks * NGRP * 32 + lane;
                uint32_t bfc[2];
                {
                    float2 v = Bk[8 * 32];
                    bfc[0] = __float_as_uint(v.x);
                    bfc[1] = __float_as_uint(v.y);
                }
#pragma unroll
                for (int g = 0; g < 8; ++g) {
                    uint32_t bf[2];
                    float2 v = Bk[g * 32];
                    bf[0] = __float_as_uint(v.x);
                    bf[1] = __float_as_uint(v.y);
                    mma_tf32(acc[g], af, bf);
                }
                mma_tf32(accV, af, bfc);        // values
            }
            BAR_ARRIVE(BFREE0 + buf, NTHR);     // buffer free (non-blocking)
        }

        // ---- register epilogue: g_v / g_ratio / g_ent ----
        float ent2 = 0.f;
#pragma unroll
        for (int half = 0; half < 2; ++half) {
            float tl[8][2];
            float m = -1e30f;
#pragma unroll
            for (int g = 0; g < 8; ++g) {
                tl[g][0] = acc[g][half * 2]     + bias[g].x;
                tl[g][1] = acc[g][half * 2 + 1] + bias[g].y;
                m = fmaxf(m, fmaxf(tl[g][0], tl[g][1]));
            }
            m = fmaxf(m, __shfl_xor_sync(0xffffffffu, m, 1));
            m = fmaxf(m, __shfl_xor_sync(0xffffffffu, m, 2));

            float se = 0.f, pe = 0.f;
#pragma unroll
            for (int g = 0; g < 8; ++g) {
#pragma unroll
                for (int b = 0; b < 2; ++b) {
                    float t2 = tl[g][b] - m;
                    tl[g][b] = t2;
                    float e = __expf(t2);
                    se += e;
                    pe = fmaf(e, t2, pe);
                }
            }
            se += __shfl_xor_sync(0xffffffffu, se, 1);
            se += __shfl_xor_sync(0xffffffffu, se, 2);
            pe += __shfl_xor_sync(0xffffffffu, pe, 1);
            pe += __shfl_xor_sync(0xffffffffu, pe, 2);

            const int r = 16 * w + q + half * 8;
            const int grow = row0 + r;
            const int a = __ldg(actions + grow);
            float cand = -1e30f;
            if (j == ((a >> 1) & 3)) {
                const int ga = a >> 3, ba = a & 1;
#pragma unroll
                for (int g = 0; g < 8; ++g)
                    if (g == ga) cand = ba ? tl[g][1] : tl[g][0];
            }
            cand = fmaxf(cand, __shfl_xor_sync(0xffffffffu, cand, 1));
            cand = fmaxf(cand, __shfl_xor_sync(0xffffffffu, cand, 2));

            if (j == 0) {
                const float logse = __logf(se);
                g_ratio[grow] = __expf(cand - logse - __ldg(log_probs + grow));
                g_v[grow] = accV[half * 2] + cb;
                ent2 += logse - pe / se;
            }
        }
#pragma unroll
        for (int o = 16; o > 0; o >>= 1) ent2 += __shfl_xor_sync(0xffffffffu, ent2, o);
        if (lane == 0) sEnt[w] = ent2;
        BAR_SYNC(BEPI, NCONS);
        if (tid == 0) {
            float s8 = 0.f;
#pragma unroll
            for (int i2 = 0; i2 < 8; ++i2) s8 += sEnt[i2];
            g_ent[cur] = s8;
        }
    }
}

// ---------------------------------------------------------------------------
// GAE: deltas inline from g_v / g_nv, spin-synced exchange.
// ---------------------------------------------------------------------------
__device__ __forceinline__ void thread_affine(const float* __restrict__ rewards,
                                              const int* __restrict__ dones,
                                              int base, float (&d)[8], float (&c)[8],
                                              float& A, float& Bv) {
    float4 v0 = *(const float4*)&g_v[base];
    float4 v1 = *(const float4*)&g_v[base + 4];
    float4 n0 = *(const float4*)&g_nv[base];
    float4 n1 = *(const float4*)&g_nv[base + 4];
    float4 r0 = *(const float4*)&rewards[base];
    float4 r1 = *(const float4*)&rewards[base + 4];
    int4 q0 = *(const int4*)&dones[base];
    int4 q1 = *(const int4*)&dones[base + 4];
    float nd[8] = {1.f-(float)q0.x, 1.f-(float)q0.y, 1.f-(float)q0.z, 1.f-(float)q0.w,
                   1.f-(float)q1.x, 1.f-(float)q1.y, 1.f-(float)q1.z, 1.f-(float)q1.w};
    float vv[8] = {v0.x, v0.y, v0.z, v0.w, v1.x, v1.y, v1.z, v1.w};
    float nn[8] = {n0.x, n0.y, n0.z, n0.w, n1.x, n1.y, n1.z, n1.w};
    float rr[8] = {r0.x, r0.y, r0.z, r0.w, r1.x, r1.y, r1.z, r1.w};
#pragma unroll
    for (int i = 0; i < 8; ++i) {
        d[i] = rr[i] + GAMMA_F * nn[i] * nd[i] - vv[i];
        c[i] = GL_F * nd[i];
    }
    A = 1.f; Bv = 0.f;
#pragma unroll
    for (int jj = 7; jj >= 0; --jj) { Bv = fmaf(c[jj], Bv, d[jj]); A = c[jj] * A; }
}

__global__ void __launch_bounds__(256)
kgae(const float* __restrict__ rewards, const int* __restrict__ dones,
     int nb, float* __restrict__ out, int T, int nb1) {
    __shared__ float sa[256], sb[256];
    __shared__ float ca[NB_MAX], cbv[NB_MAX];
    __shared__ float sv_[256];
    __shared__ int sdone;
    const int tid = threadIdx.x;
    const int blk = blockIdx.x;
    const int base = blk * CHUNK + tid * 8;

    float d[8], c[8], A, Bv;
    thread_affine(rewards, dones, base, d, c, A, Bv);

    sa[tid] = A; sb[tid] = Bv;
    __syncthreads();
    for (int dd = 1; dd < 256; dd <<= 1) {
        float al = sa[tid], bl = sb[tid];
        float ar = 1.f, br = 0.f;
        if (tid + dd < 256) { ar = sa[tid + dd]; br = sb[tid + dd]; }
        __syncthreads();
        sa[tid] = al * ar;
        sb[tid] = fmaf(al, br, bl);
        __syncthreads();
    }

    if (tid == 0) {
        g_cA[blk] = sa[0];
        g_cB[blk] = sb[0];
        __threadfence();
        atomicAdd(&g_flag, 1);
        while (*(volatile int*)&g_flag < nb) { }
    }
    __syncthreads();
    __threadfence();

    if (tid < NB_MAX) { ca[tid] = g_cA[tid]; cbv[tid] = g_cB[tid]; }
    __syncthreads();
    for (int dd = 1; dd < NB_MAX; dd <<= 1) {
        float a = 0.f, b = 0.f, ar = 1.f, br = 0.f;
        if (tid < NB_MAX) {
            a = ca[tid]; b = cbv[tid];
            if (tid + dd < NB_MAX) { ar = ca[tid + dd]; br = cbv[tid + dd]; }
        }
        __syncthreads();
        if (tid < NB_MAX) { ca[tid] = a * ar; cbv[tid] = fmaf(a, br, b); }
        __syncthreads();
    }
    const float xb = (blk + 1 < nb) ? cbv[blk + 1] : 0.f;
    float xin = (tid == 255) ? xb : fmaf(sa[tid + 1], xb, sb[tid + 1]);

    float4 r0 = *(const float4*)&g_ratio[base];
    float4 r1 = *(const float4*)&g_ratio[base + 4];
    float rt[8] = {r0.x, r0.y, r0.z, r0.w, r1.x, r1.y, r1.z, r1.w};

    float adv = xin, s1 = 0.f, s2 = 0.f;
#pragma unroll
    for (int jj = 7; jj >= 0; --jj) {
        adv = fmaf(c[jj], adv, d[jj]);
        const float r = rt[jj];
        const float rc = fminf(fmaxf(r, CLIP_LO), CLIP_HI);
        s1 += fminf(r * adv, rc * adv);
        s2 = fmaf(adv, adv, s2);
    }
    __syncthreads();
    sa[tid] = s1; sb[tid] = s2;
    __syncthreads();
    for (int s = 128; s > 0; s >>= 1) {
        if (tid < s) { sa[tid] += sa[tid + s]; sb[tid] += sb[tid + s]; }
        __syncthreads();
    }
    if (tid == 0) {
        g_surr[blk] = sa[0];
        g_adv2[blk] = sb[0];
        __threadfence();
        sdone = atomicAdd(&g_flag2, 1);
    }
    __syncthreads();

    if (sdone == nb - 1) {
        __threadfence();
        float e = 0.f, s = 0.f, v = 0.f;
        for (int i = tid; i < nb1; i += 256) e += g_ent[i];
        for (int i = tid; i < nb; i += 256) { s += g_surr[i]; v += g_adv2[i]; }
        __syncthreads();
        sa[tid] = e; sb[tid] = s; sv_[tid] = v;
        __syncthreads();
        for (int st = 128; st > 0; st >>= 1) {
            if (tid < st) {
                sa[tid] += sa[tid + st];
                sb[tid] += sb[tid + st];
                sv_[tid] += sv_[tid + st];
            }
            __syncthreads();
        }
        if (tid == 0) {
            const float invT = 1.f / (float)T;
            out[0] = -(sb[0] * invT) - ENT_C * (sa[0] * invT);
            out[1] = sv_[0] * invT;
        }
    }
}

extern "C" void kernel_launch(void* const* d_in, const int* in_sizes, int n_in,
                              void* d_out, int out_size) {
    const float* states      = (const float*)d_in[0];
    const float* next_states = (const float*)d_in[1];
    const float* rewards     = (const float*)d_in[2];
    const int*   dones       = (const int*)  d_in[3];
    const int*   actions     = (const int*)  d_in[4];
    const float* log_probs   = (const float*)d_in[5];
    const float* actor_w     = (const float*)d_in[6];
    const float* actor_b     = (const float*)d_in[7];
    const float* critic_w    = (const float*)d_in[8];
    const float* critic_b    = (const float*)d_in[9];
    float* out = (float*)d_out;

    const int T   = in_sizes[2];
    const int nb1 = T / BM;       // 2048
    const int nb  = T / CHUNK;    // 128
    const int grid1 = nb1 < GRID1 ? nb1 : GRID1;

    cudaFuncSetAttribute(k1_mma, cudaFuncAttributeMaxDynamicSharedMemorySize, SMEM_TOTAL);

    kprep<<<(64 * NGRP * 32) / 256, 256>>>(actor_w, critic_w);
    k1_mma<<<grid1, NTHR, SMEM_TOTAL>>>(states, next_states, actions, log_probs,
                                        actor_b, critic_w, critic_b, nb1);
    kgae<<<nb, 256>>>(rewards, dones, nb, out, T, nb1);
}